// round 1
// baseline (speedup 1.0000x reference)
#include <cuda_runtime.h>
#include <cstdint>

// LIF scan: B=2048 rows, T=4096 steps. One lane per row, sequential over t.
// Outputs: v_rec [B,T], s_rec [B,T], dv [B,T] concatenated in d_out.

static constexpr int T_LEN  = 4096;
static constexpr int TC     = 64;    // time chunk per cp.async stage
static constexpr int ROWS   = 32;    // rows per block (one warp)
static constexpr int STRIDE = 68;    // padded floats per row in shared tile (17*4)
static constexpr float VTH  = 1.27f;

__device__ __forceinline__ void issue_chunk_cp(const float* gsrc, unsigned sdst)
{
    // Copy TC floats (this lane's row slice) global -> shared, 16B at a time.
#pragma unroll
    for (int j = 0; j < TC / 4; ++j) {
        asm volatile("cp.async.ca.shared.global [%0], [%1], 16;\n"
                     :: "r"(sdst + j * 16), "l"(gsrc + j * 4));
    }
    asm volatile("cp.async.commit_group;\n");
}

__global__ void __launch_bounds__(ROWS)
lif_scan_kernel(const float* __restrict__ ode,
                const float* __restrict__ decay_p,
                float* __restrict__ v_out,
                float* __restrict__ s_out)
{
    __shared__ float tile[2][ROWS][STRIDE];

    const int lane = threadIdx.x;
    const int row  = blockIdx.x * ROWS + lane;
    const float dec = *decay_p;

    const float* src  = ode   + (size_t)row * T_LEN;
    float*       vdst = v_out + (size_t)row * T_LEN;
    float*       sdst = s_out + (size_t)row * T_LEN;

    const unsigned sbase0 = (unsigned)__cvta_generic_to_shared(&tile[0][lane][0]);
    const unsigned sbase1 = (unsigned)__cvta_generic_to_shared(&tile[1][lane][0]);

    constexpr int NCH = T_LEN / TC;

    issue_chunk_cp(src + 0 * TC, sbase0);
    issue_chunk_cp(src + 1 * TC, sbase1);

    float v = 0.0f;   // membrane potential (V_REST = 0)
    int   c = 0;      // refractory counter, in {0,1,2}
    int   z = 0;      // input-zeroing countdown, in {0..5}

    for (int k = 0; k < NCH; ++k) {
        if (k == NCH - 1) {
            asm volatile("cp.async.wait_group 0;\n" ::: "memory");
        } else {
            asm volatile("cp.async.wait_group 1;\n" ::: "memory");
        }

        const int buf = k & 1;
        const float* trow = &tile[buf][lane][0];
        const int t0 = k * TC;

#pragma unroll 4
        for (int i = 0; i < TC; i += 4) {
            float4 x4 = *reinterpret_cast<const float4*>(trow + i);
            float xs[4] = {x4.x, x4.y, x4.z, x4.w};
            float vs[4], ss[4];
#pragma unroll
            for (int q = 0; q < 4; ++q) {
                const int t = t0 + i + q;
                const float x  = xs[q];
                const float xe = (z > 0) ? 0.0f : x;       // input zeroed inside window
                const float vd = fmaf(-dec, v, v);         // v - decay*(v - V_REST)
                const float a  = vd + xe;
                const float b  = (c == 1) ? xe : a;        // reset to V_RESET(=0) + x_eff
                const float t2 = (c >= 2) ? VTH : b;       // refractory clamp
                const bool  s  = t2 > VTH;                 // spike(v - V_TH)
                v = fminf(t2, VTH);                        // == where(counter>1, VTH, v)
                vs[q] = v;
                ss[q] = s ? 1.0f : 0.0f;
                c = s ? (c + 1) : max(c - 1, 0);           // max(c + 2s - 1, 0)
                z = s ? ((t > 0) ? 5 : 0) : max(z - 1, 0); // spike at t=0 zeroes nothing
            }
            float4 v4 = make_float4(vs[0], vs[1], vs[2], vs[3]);
            float4 s4 = make_float4(ss[0], ss[1], ss[2], ss[3]);
            *reinterpret_cast<float4*>(vdst + t0 + i) = v4;
            *reinterpret_cast<float4*>(sdst + t0 + i) = s4;
        }

        if (k + 2 < NCH) {
            issue_chunk_cp(src + (k + 2) * TC, buf ? sbase1 : sbase0);
        }
    }
}

// dv[b,j] = ode[b,j] unless a spike occurred at t' in [j-5, j+1] with t' >= 1.
static constexpr int SEG = 1024;

__global__ void __launch_bounds__(256)
lif_dv_kernel(const float* __restrict__ ode,
              const float* __restrict__ s,
              float* __restrict__ dv)
{
    __shared__ float ssh[SEG + 8];

    const int rowB = blockIdx.y;
    const int seg0 = blockIdx.x * SEG;

    const float* srow = s + (size_t)rowB * T_LEN;

    // Load s[seg0-5 .. seg0+SEG] (SEG+6 values). Out-of-range and t'==0 read as 0.
    for (int idx = threadIdx.x; idx < SEG + 6; idx += blockDim.x) {
        const int col = seg0 - 5 + idx;
        ssh[idx] = (col >= 1 && col < T_LEN) ? srow[col] : 0.0f;
    }
    __syncthreads();

    const float* orow = ode + (size_t)rowB * T_LEN;
    float*       drow = dv  + (size_t)rowB * T_LEN;

    const int j0 = threadIdx.x * 4;
    float4 o4 = *reinterpret_cast<const float4*>(orow + seg0 + j0);
    float ov[4] = {o4.x, o4.y, o4.z, o4.w};
    float rv[4];
#pragma unroll
    for (int q = 0; q < 4; ++q) {
        const int j = j0 + q;
        float acc = 0.0f;
#pragma unroll
        for (int kk = 0; kk < 7; ++kk) acc += ssh[j + kk];  // cols j-5 .. j+1
        rv[q] = (acc > 0.0f) ? 0.0f : ov[q];
    }
    float4 r4 = make_float4(rv[0], rv[1], rv[2], rv[3]);
    *reinterpret_cast<float4*>(drow + seg0 + j0) = r4;
}

extern "C" void kernel_launch(void* const* d_in, const int* in_sizes, int n_in,
                              void* d_out, int out_size)
{
    const float* ode     = (const float*)d_in[0];
    const float* decay_p = (const float*)d_in[1];
    float*       out     = (float*)d_out;

    const int BT = in_sizes[0];          // B*T (trailing dim is 1)
    const int B  = BT / T_LEN;

    float* v_out  = out;
    float* s_out  = out + (size_t)BT;
    float* dv_out = out + (size_t)2 * BT;

    lif_scan_kernel<<<B / ROWS, ROWS>>>(ode, decay_p, v_out, s_out);

    dim3 dvgrid(T_LEN / SEG, B);
    lif_dv_kernel<<<dvgrid, 256>>>(ode, s_out, dv_out);
}

// round 2
// speedup vs baseline: 1.0045x; 1.0045x over previous
#include <cuda_runtime.h>
#include <cstdint>

// LIF scan: B=2048 rows, T=4096 steps. One lane per row, sequential over t.
// Outputs: v_rec [B,T], s_rec [B,T], dv [B,T] concatenated in d_out.

static constexpr int T_LEN  = 4096;
static constexpr int TC     = 64;    // time chunk per cp.async stage
static constexpr int ROWS   = 32;    // rows per block (one warp)
static constexpr int STRIDE = 68;    // padded floats per row in shared tile (17*4)
static constexpr float VTH  = 1.27f;

__device__ __forceinline__ void issue_chunk_cp(const float* gsrc, unsigned sdst)
{
    // Copy TC floats (this lane's row slice) global -> shared, 16B at a time.
#pragma unroll
    for (int j = 0; j < TC / 4; ++j) {
        asm volatile("cp.async.ca.shared.global [%0], [%1], 16;\n"
                     :: "r"(sdst + j * 16), "l"(gsrc + j * 4));
    }
    asm volatile("cp.async.commit_group;\n");
}

__global__ void __launch_bounds__(ROWS)
lif_scan_kernel(const float* __restrict__ ode,
                const float* __restrict__ decay_p,
                float* __restrict__ v_out,
                float* __restrict__ s_out)
{
    __shared__ float tile[2][ROWS][STRIDE];

    const int lane = threadIdx.x;
    const int row  = blockIdx.x * ROWS + lane;
    const float dec = *decay_p;

    const float* src  = ode   + (size_t)row * T_LEN;
    float*       vdst = v_out + (size_t)row * T_LEN;
    float*       sdst = s_out + (size_t)row * T_LEN;

    const unsigned sbase0 = (unsigned)__cvta_generic_to_shared(&tile[0][lane][0]);
    const unsigned sbase1 = (unsigned)__cvta_generic_to_shared(&tile[1][lane][0]);

    constexpr int NCH = T_LEN / TC;

    issue_chunk_cp(src + 0 * TC, sbase0);
    issue_chunk_cp(src + 1 * TC, sbase1);

    float v = 0.0f;   // membrane potential (V_REST = 0)
    int   c = 0;      // refractory counter, in {0,1,2}
    int   z = 0;      // input-zeroing countdown, in {0..5}

    for (int k = 0; k < NCH; ++k) {
        if (k == NCH - 1) {
            asm volatile("cp.async.wait_group 0;\n" ::: "memory");
        } else {
            asm volatile("cp.async.wait_group 1;\n" ::: "memory");
        }

        const int buf = k & 1;
        const float* trow = &tile[buf][lane][0];
        const int t0 = k * TC;

#pragma unroll 4
        for (int i = 0; i < TC; i += 4) {
            float4 x4 = *reinterpret_cast<const float4*>(trow + i);
            float xs[4] = {x4.x, x4.y, x4.z, x4.w};
            float vs[4], ss[4];
#pragma unroll
            for (int q = 0; q < 4; ++q) {
                const int t = t0 + i + q;
                const float x  = xs[q];
                const float xe = (z > 0) ? 0.0f : x;       // input zeroed inside window
                const float vd = fmaf(-dec, v, v);         // v - decay*(v - V_REST)
                const float a  = vd + xe;
                const float b  = (c == 1) ? xe : a;        // reset to V_RESET(=0) + x_eff
                const float t2 = (c >= 2) ? VTH : b;       // refractory clamp
                const bool  s  = t2 > VTH;                 // spike(v - V_TH)
                v = fminf(t2, VTH);                        // == where(counter>1, VTH, v)
                vs[q] = v;
                ss[q] = s ? 1.0f : 0.0f;
                c = s ? (c + 1) : max(c - 1, 0);           // max(c + 2s - 1, 0)
                z = s ? ((t > 0) ? 5 : 0) : max(z - 1, 0); // spike at t=0 zeroes nothing
            }
            float4 v4 = make_float4(vs[0], vs[1], vs[2], vs[3]);
            float4 s4 = make_float4(ss[0], ss[1], ss[2], ss[3]);
            *reinterpret_cast<float4*>(vdst + t0 + i) = v4;
            *reinterpret_cast<float4*>(sdst + t0 + i) = s4;
        }

        if (k + 2 < NCH) {
            issue_chunk_cp(src + (k + 2) * TC, buf ? sbase1 : sbase0);
        }
    }
}

// dv[b,j] = ode[b,j] unless a spike occurred at t' in [j-5, j+1] with t' >= 1.
static constexpr int SEG = 1024;

__global__ void __launch_bounds__(256)
lif_dv_kernel(const float* __restrict__ ode,
              const float* __restrict__ s,
              float* __restrict__ dv)
{
    __shared__ float ssh[SEG + 8];

    const int rowB = blockIdx.y;
    const int seg0 = blockIdx.x * SEG;

    const float* srow = s + (size_t)rowB * T_LEN;

    // Load s[seg0-5 .. seg0+SEG] (SEG+6 values). Out-of-range and t'==0 read as 0.
    for (int idx = threadIdx.x; idx < SEG + 6; idx += blockDim.x) {
        const int col = seg0 - 5 + idx;
        ssh[idx] = (col >= 1 && col < T_LEN) ? srow[col] : 0.0f;
    }
    __syncthreads();

    const float* orow = ode + (size_t)rowB * T_LEN;
    float*       drow = dv  + (size_t)rowB * T_LEN;

    const int j0 = threadIdx.x * 4;
    float4 o4 = *reinterpret_cast<const float4*>(orow + seg0 + j0);
    float ov[4] = {o4.x, o4.y, o4.z, o4.w};
    float rv[4];
#pragma unroll
    for (int q = 0; q < 4; ++q) {
        const int j = j0 + q;
        float acc = 0.0f;
#pragma unroll
        for (int kk = 0; kk < 7; ++kk) acc += ssh[j + kk];  // cols j-5 .. j+1
        rv[q] = (acc > 0.0f) ? 0.0f : ov[q];
    }
    float4 r4 = make_float4(rv[0], rv[1], rv[2], rv[3]);
    *reinterpret_cast<float4*>(drow + seg0 + j0) = r4;
}

extern "C" void kernel_launch(void* const* d_in, const int* in_sizes, int n_in,
                              void* d_out, int out_size)
{
    const float* ode     = (const float*)d_in[0];
    const float* decay_p = (const float*)d_in[1];
    float*       out     = (float*)d_out;

    const int BT = in_sizes[0];          // B*T (trailing dim is 1)
    const int B  = BT / T_LEN;

    float* v_out  = out;
    float* s_out  = out + (size_t)BT;
    float* dv_out = out + (size_t)2 * BT;

    lif_scan_kernel<<<B / ROWS, ROWS>>>(ode, decay_p, v_out, s_out);

    dim3 dvgrid(T_LEN / SEG, B);
    lif_dv_kernel<<<dvgrid, 256>>>(ode, s_out, dv_out);
}

// round 3
// speedup vs baseline: 1.4684x; 1.4618x over previous
#include <cuda_runtime.h>
#include <cstdint>

static constexpr int   T_LEN = 4096;
static constexpr int   TC    = 32;            // steps per chunk
static constexpr int   NCH   = T_LEN / TC;    // 128
static constexpr int   ROWS  = 32;            // rows per block (one lane each)
static constexpr int   D     = 6;             // x-tile ring depth
static constexpr int   STRW  = 36;            // padded words/row (conflict-free LDS.128)
static constexpr float VTH   = 1.27f;

__device__ __forceinline__ void cp_chunk(const float* g, float* s)
{
    unsigned sa = (unsigned)__cvta_generic_to_shared(s);
#pragma unroll
    for (int j = 0; j < TC / 4; ++j)
        asm volatile("cp.async.ca.shared.global [%0], [%1], 16;\n"
                     :: "r"(sa + 16 * j), "l"(g + 4 * j));
    asm volatile("cp.async.commit_group;\n");
}

__global__ void __launch_bounds__(96)
lif_fused(const float* __restrict__ ode, const float* __restrict__ decay_p,
          float* __restrict__ v_out, float* __restrict__ s_out,
          float* __restrict__ dv_out)
{
    __shared__ float    xt[D][ROWS][STRW];  // input chunks (ring)
    __shared__ float    vb[2][ROWS][STRW];  // v values (double buffer)
    __shared__ unsigned sb[4][ROWS];        // spike bitmask per chunk (ring)

    const int wid  = threadIdx.x >> 5;
    const int lane = threadIdx.x & 31;
    const int row  = blockIdx.x * ROWS + lane;
    const size_t rb = (size_t)row * T_LEN;
    const float dec = __ldg(decay_p);
    const float* xg = ode + rb;

    // scan state (w0): aa = pre-clamp value of last step, pA = spike there,
    // S bit j = spike at (t-2-j) when computing step t.
    float aa = 0.0f; unsigned S = 0u; bool pA = false;

    if (wid == 1) {
        cp_chunk(xg + 0 * TC, &xt[0][lane][0]);
        cp_chunk(xg + 1 * TC, &xt[1][lane][0]);
        cp_chunk(xg + 2 * TC, &xt[2][lane][0]);
        asm volatile("cp.async.wait_group 2;\n" ::: "memory");
    }
    __syncthreads();

    for (int k = 0; k < NCH + 2; ++k) {
        // ---------------- w0: scan chunk k ----------------
        if (wid == 0 && k < NCH) {
            const float* xr = &xt[k % D][lane][0];
            float*       vr = &vb[k & 1][lane][0];
            unsigned bits = 0u;
            if (k == 0) {
                // general machine: handles t=0 edge (spike at 0 sets no window)
                float v = 0.0f, t2 = 0.0f; int c = 0, z = 0; bool s = false;
#pragma unroll 4
                for (int t = 0; t < TC; ++t) {
                    float x  = xr[t];
                    float xe = (z > 0) ? 0.0f : x;
                    float vd = fmaf(-dec, v, v);
                    float a  = vd + xe;
                    float b  = (c == 1) ? xe : a;
                    t2 = (c >= 2) ? VTH : b;
                    s  = t2 > VTH;
                    v  = fminf(t2, VTH);
                    vr[t] = v;
                    bits |= s ? (1u << t) : 0u;
                    c = s ? (c + 1) : (c > 0 ? c - 1 : 0);
                    z = s ? (t > 0 ? 5 : z) : (z > 0 ? z - 1 : 0);
                }
                aa = t2; pA = s;
                S  = (__brev(bits) >> 1) & 0xFu;   // bits 30,29,28,27
            } else {
#pragma unroll
                for (int g4 = 0; g4 < TC / 4; ++g4) {
                    float4 x4 = *reinterpret_cast<const float4*>(xr + 4 * g4);
                    float xs[4] = {x4.x, x4.y, x4.z, x4.w};
                    float vs[4];
#pragma unroll
                    for (int q = 0; q < 4; ++q) {
                        const int t = 4 * g4 + q;
                        float xm  = ((S & 0xFu) != 0u) ? 0.0f : xs[q]; // window t-5..t-2
                        float vd  = fmaf(-dec, aa, aa);
                        float sum = vd + xm;
                        float aan = pA ? 0.0f : sum;   // spike at t-1 -> exact 0
                        bool  pN  = aan > VTH;
                        vs[q] = fminf(aan, VTH);
                        bits |= pN ? (1u << t) : 0u;
                        S = (S << 1) | (pA ? 1u : 0u);
                        aa = aan; pA = pN;
                    }
                    *reinterpret_cast<float4*>(vr + 4 * g4) =
                        make_float4(vs[0], vs[1], vs[2], vs[3]);
                }
            }
            sb[k & 3][lane] = bits;
        }

        // ------------- w1: prefetch + v/s store (chunk k-1) -------------
        if (wid == 1) {
            if (k + 3 < NCH)
                cp_chunk(xg + (size_t)(k + 3) * TC, &xt[(k + 3) % D][lane][0]);
            const int c = k - 1;
            if (c >= 0 && c < NCH) {
                const float* vr = &vb[c & 1][lane][0];
                const unsigned m = sb[c & 3][lane];
                float* vg = v_out + rb + (size_t)c * TC;
                float* sg = s_out + rb + (size_t)c * TC;
#pragma unroll
                for (int g4 = 0; g4 < TC / 4; ++g4) {
                    *reinterpret_cast<float4*>(vg + 4 * g4) =
                        *reinterpret_cast<const float4*>(vr + 4 * g4);
                    float sf[4];
#pragma unroll
                    for (int q = 0; q < 4; ++q) {
                        const int t = 4 * g4 + q;
                        sf[q] = __int_as_float(((int)(m << (31 - t)) >> 31) & 0x3f800000);
                    }
                    *reinterpret_cast<float4*>(sg + 4 * g4) =
                        make_float4(sf[0], sf[1], sf[2], sf[3]);
                }
            }
            asm volatile("cp.async.wait_group 2;\n" ::: "memory");
        }

        // ------------- w2: dv (chunk k-2) -------------
        if (wid == 2) {
            const int c = k - 2;
            if (c >= 0 && c < NCH) {
                unsigned m  = sb[c & 3][lane];
                unsigned mp = (c > 0) ? sb[(c - 1) & 3][lane] : 0u;
                unsigned mn = (c + 1 < NCH) ? (sb[(c + 1) & 3][lane] & 1u) : 0u;
                if (c == 0) m  &= ~1u;   // spike at t=0 zeroes nothing
                if (c == 1) mp &= ~1u;
                // W bit i = spike at (t0-5+i); zero dv[t0+j] iff any bit j..j+6
                unsigned long long W = ((unsigned long long)m << 5) | (mp >> 27)
                                     | ((unsigned long long)mn << 37);
                W |= W >> 1; W |= W >> 2; W |= W >> 3;
                const unsigned V = (unsigned)W;
                const float* xr = &xt[c % D][lane][0];
                float* dg = dv_out + rb + (size_t)c * TC;
#pragma unroll
                for (int g4 = 0; g4 < TC / 4; ++g4) {
                    float4 x4 = *reinterpret_cast<const float4*>(xr + 4 * g4);
                    int xb[4] = {__float_as_int(x4.x), __float_as_int(x4.y),
                                 __float_as_int(x4.z), __float_as_int(x4.w)};
                    float r[4];
#pragma unroll
                    for (int q = 0; q < 4; ++q) {
                        const int t = 4 * g4 + q;
                        int msk = (int)(V << (31 - t)) >> 31;  // ~0 iff zeroed
                        r[q] = __int_as_float(xb[q] & ~msk);
                    }
                    *reinterpret_cast<float4*>(dg + 4 * g4) =
                        make_float4(r[0], r[1], r[2], r[3]);
                }
            }
        }

        __syncthreads();
    }
}

extern "C" void kernel_launch(void* const* d_in, const int* in_sizes, int n_in,
                              void* d_out, int out_size)
{
    const float* ode     = (const float*)d_in[0];
    const float* decay_p = (const float*)d_in[1];
    float*       out     = (float*)d_out;

    const int BT = in_sizes[0];
    const int B  = BT / T_LEN;

    float* v_out  = out;
    float* s_out  = out + (size_t)BT;
    float* dv_out = out + (size_t)2 * BT;

    lif_fused<<<B / ROWS, 96>>>(ode, decay_p, v_out, s_out, dv_out);
}

// round 4
// speedup vs baseline: 1.5073x; 1.0265x over previous
#include <cuda_runtime.h>
#include <cstdint>

static constexpr int   T_LEN = 4096;
static constexpr int   TC    = 32;            // steps per chunk
static constexpr int   NCH   = T_LEN / TC;    // 128
static constexpr int   ROWS  = 32;            // rows per block (one lane each)
static constexpr int   D     = 6;             // x-tile ring depth
static constexpr int   STRW  = 36;            // padded words/row (conflict-free LDS.128)
static constexpr float VTH   = 1.27f;

__device__ __forceinline__ void cp_chunk(const float* g, float* s)
{
    unsigned sa = (unsigned)__cvta_generic_to_shared(s);
#pragma unroll
    for (int j = 0; j < TC / 4; ++j)
        asm volatile("cp.async.ca.shared.global [%0], [%1], 16;\n"
                     :: "r"(sa + 16 * j), "l"(g + 4 * j));
    asm volatile("cp.async.commit_group;\n");
}

__global__ void __launch_bounds__(96)
lif_fused(const float* __restrict__ ode, const float* __restrict__ decay_p,
          float* __restrict__ v_out, float* __restrict__ s_out,
          float* __restrict__ dv_out)
{
    __shared__ float    xt[D][ROWS][STRW];  // input chunks (ring)
    __shared__ float    vb[2][ROWS][STRW];  // v values (double buffer)
    __shared__ unsigned sb[4][ROWS];        // spike bitmask per chunk (ring)

    const int wid  = threadIdx.x >> 5;
    const int lane = threadIdx.x & 31;
    const int row  = blockIdx.x * ROWS + lane;
    const size_t rb = (size_t)row * T_LEN;
    const float dec = __ldg(decay_p);
    const float* xg = ode + rb;

    // scan state (w0): aa = pre-clamp value of previous step (as int bits for LOP3),
    // s1..s5 = full-width spike masks for steps t-1..t-5 (~0 iff spike).
    float aa = 0.0f;
    int s1 = 0, s2 = 0, s3 = 0, s4 = 0, s5 = 0;

    if (wid == 1) {
        cp_chunk(xg + 0 * TC, &xt[0][lane][0]);
        cp_chunk(xg + 1 * TC, &xt[1][lane][0]);
        cp_chunk(xg + 2 * TC, &xt[2][lane][0]);
        asm volatile("cp.async.wait_group 2;\n" ::: "memory");
    }
    __syncthreads();

    for (int k = 0; k < NCH + 2; ++k) {
        // ---------------- w0: scan chunk k ----------------
        if (wid == 0 && k < NCH) {
            const float* xr = &xt[k % D][lane][0];
            float*       vr = &vb[k & 1][lane][0];
            unsigned bits = 0u;
            if (k == 0) {
                // general machine: handles the t=0 edge (spike at 0 opens no window)
                float v = 0.0f, t2 = 0.0f; int c = 0, z = 0; bool s = false;
#pragma unroll 4
                for (int t = 0; t < TC; ++t) {
                    float x  = xr[t];
                    float xe = (z > 0) ? 0.0f : x;
                    float vd = fmaf(-dec, v, v);
                    float a  = vd + xe;
                    float b  = (c == 1) ? xe : a;
                    t2 = (c >= 2) ? VTH : b;
                    s  = t2 > VTH;
                    v  = fminf(t2, VTH);
                    vr[t] = v;
                    bits |= s ? (1u << t) : 0u;
                    c = s ? (c + 1) : (c > 0 ? c - 1 : 0);
                    z = s ? (t > 0 ? 5 : z) : (z > 0 ? z - 1 : 0);
                }
                aa = t2;
                s1 = (int)bits >> 31;          // spike at t=31
                s2 = (int)(bits << 1) >> 31;   // t=30
                s3 = (int)(bits << 2) >> 31;   // t=29
                s4 = (int)(bits << 3) >> 31;   // t=28
                s5 = (int)(bits << 4) >> 31;   // t=27
            } else {
#pragma unroll
                for (int g4 = 0; g4 < TC / 4; ++g4) {
                    float4 x4 = *reinterpret_cast<const float4*>(xr + 4 * g4);
                    float xs[4] = {x4.x, x4.y, x4.z, x4.w};
                    float vs[4];
#pragma unroll
                    for (int q = 0; q < 4; ++q) {
                        const int t = 4 * g4 + q;
                        // window t-5..t-2 (two LOP3s, one iteration of slack)
                        int w1m = s2 | s3 | s4;
                        int xm  = __float_as_int(xs[q]) & ~(w1m | s5);
                        // critical chain: FFMA -> FADD -> LOP3
                        float vd  = fmaf(-dec, aa, aa);
                        float sum = vd + __int_as_float(xm);
                        float aan = __int_as_float(__float_as_int(sum) & ~s1);
                        // spike mask side-path (FADD -> SHF)
                        int   sm  = __float_as_int(VTH - aan) >> 31;
                        vs[q] = fminf(aan, VTH);
                        bits |= (1u << t) & (unsigned)sm;
                        // rotate history (register-renamed by unroll)
                        s5 = s4; s4 = s3; s3 = s2; s2 = s1; s1 = sm;
                        aa = aan;
                    }
                    *reinterpret_cast<float4*>(vr + 4 * g4) =
                        make_float4(vs[0], vs[1], vs[2], vs[3]);
                }
            }
            sb[k & 3][lane] = bits;
        }

        // ------------- w1: prefetch + v/s store (chunk k-1) -------------
        if (wid == 1) {
            if (k + 3 < NCH)
                cp_chunk(xg + (size_t)(k + 3) * TC, &xt[(k + 3) % D][lane][0]);
            const int c = k - 1;
            if (c >= 0 && c < NCH) {
                const float* vr = &vb[c & 1][lane][0];
                const unsigned m = sb[c & 3][lane];
                float* vg = v_out + rb + (size_t)c * TC;
                float* sg = s_out + rb + (size_t)c * TC;
#pragma unroll
                for (int g4 = 0; g4 < TC / 4; ++g4) {
                    *reinterpret_cast<float4*>(vg + 4 * g4) =
                        *reinterpret_cast<const float4*>(vr + 4 * g4);
                    float sf[4];
#pragma unroll
                    for (int q = 0; q < 4; ++q) {
                        const int t = 4 * g4 + q;
                        sf[q] = __int_as_float(((int)(m << (31 - t)) >> 31) & 0x3f800000);
                    }
                    *reinterpret_cast<float4*>(sg + 4 * g4) =
                        make_float4(sf[0], sf[1], sf[2], sf[3]);
                }
            }
            asm volatile("cp.async.wait_group 2;\n" ::: "memory");
        }

        // ------------- w2: dv (chunk k-2) -------------
        if (wid == 2) {
            const int c = k - 2;
            if (c >= 0 && c < NCH) {
                unsigned m  = sb[c & 3][lane];
                unsigned mp = (c > 0) ? sb[(c - 1) & 3][lane] : 0u;
                unsigned mn = (c + 1 < NCH) ? (sb[(c + 1) & 3][lane] & 1u) : 0u;
                if (c == 0) m  &= ~1u;   // spike at t=0 zeroes nothing
                if (c == 1) mp &= ~1u;
                // W bit i = spike at (t0-5+i); zero dv[t0+j] iff any bit j..j+6
                unsigned long long W = ((unsigned long long)m << 5) | (mp >> 27)
                                     | ((unsigned long long)mn << 37);
                W |= W >> 1; W |= W >> 2; W |= W >> 3;
                const unsigned V = (unsigned)W;
                const float* xr = &xt[c % D][lane][0];
                float* dg = dv_out + rb + (size_t)c * TC;
#pragma unroll
                for (int g4 = 0; g4 < TC / 4; ++g4) {
                    float4 x4 = *reinterpret_cast<const float4*>(xr + 4 * g4);
                    int xb[4] = {__float_as_int(x4.x), __float_as_int(x4.y),
                                 __float_as_int(x4.z), __float_as_int(x4.w)};
                    float r[4];
#pragma unroll
                    for (int q = 0; q < 4; ++q) {
                        const int t = 4 * g4 + q;
                        int msk = (int)(V << (31 - t)) >> 31;  // ~0 iff zeroed
                        r[q] = __int_as_float(xb[q] & ~msk);
                    }
                    *reinterpret_cast<float4*>(dg + 4 * g4) =
                        make_float4(r[0], r[1], r[2], r[3]);
                }
            }
        }

        __syncthreads();
    }
}

extern "C" void kernel_launch(void* const* d_in, const int* in_sizes, int n_in,
                              void* d_out, int out_size)
{
    const float* ode     = (const float*)d_in[0];
    const float* decay_p = (const float*)d_in[1];
    float*       out     = (float*)d_out;

    const int BT = in_sizes[0];
    const int B  = BT / T_LEN;

    float* v_out  = out;
    float* s_out  = out + (size_t)BT;
    float* dv_out = out + (size_t)2 * BT;

    lif_fused<<<B / ROWS, 96>>>(ode, decay_p, v_out, s_out, dv_out);
}

// round 5
// speedup vs baseline: 1.7678x; 1.1728x over previous
#include <cuda_runtime.h>
#include <cstdint>

static constexpr int   T_LEN = 4096;
static constexpr int   TC    = 32;            // steps per chunk
static constexpr int   NCH   = T_LEN / TC;    // 128
static constexpr int   ROWS  = 32;            // rows per block
static constexpr int   D     = 6;             // x-tile ring depth
static constexpr int   STRW  = 36;            // padded words/row (bank-safe)
static constexpr float VTH   = 1.27f;

// Coalesced chunk load: lane (q,m) loads row 4r+q, bytes 16m, for r=0..7.
// Each cp.async warp-op covers 4 rows x 128B = 4 full lines (4 wavefronts).
__device__ __forceinline__ void cp_chunk(const float* gchunk, float* stile,
                                         int q, int m)
{
#pragma unroll
    for (int r = 0; r < 8; ++r) {
        const int rr = 4 * r + q;
        unsigned sa = (unsigned)__cvta_generic_to_shared(stile + rr * STRW + 4 * m);
        asm volatile("cp.async.ca.shared.global [%0], [%1], 16;\n"
                     :: "r"(sa), "l"(gchunk + (size_t)rr * T_LEN + 4 * m));
    }
    asm volatile("cp.async.commit_group;\n");
}

__global__ void __launch_bounds__(96)
lif_fused(const float* __restrict__ ode, const float* __restrict__ decay_p,
          float* __restrict__ v_out, float* __restrict__ s_out,
          float* __restrict__ dv_out)
{
    __shared__ float    xt[D][ROWS][STRW];  // input chunks (ring)
    __shared__ float    vb[2][ROWS][STRW];  // v values (double buffer)
    __shared__ unsigned sb[4][ROWS];        // spike bitmask per chunk (ring)
    __shared__ unsigned Wsh[ROWS];          // dv zero-window mask per row

    const int wid  = threadIdx.x >> 5;
    const int lane = threadIdx.x & 31;
    const int q    = lane >> 3;             // 0..3 : row group
    const int m    = lane & 7;              // 0..7 : 16B segment in chunk
    const int row0 = blockIdx.x * ROWS;
    const float dec = __ldg(decay_p);
    const float* xg0 = ode + (size_t)row0 * T_LEN;

    // scan state (w0): aa = pre-clamp value of previous step,
    // s1..s5 = spike masks (~0 iff spike) for steps t-1..t-5.
    float aa = 0.0f;
    int s1 = 0, s2 = 0, s3 = 0, s4 = 0, s5 = 0;

    if (wid == 1) {
        cp_chunk(xg0 + 0 * TC, &xt[0][0][0], q, m);
        cp_chunk(xg0 + 1 * TC, &xt[1][0][0], q, m);
        cp_chunk(xg0 + 2 * TC, &xt[2][0][0], q, m);
        asm volatile("cp.async.wait_group 2;\n" ::: "memory");
    }
    __syncthreads();

    for (int k = 0; k < NCH + 2; ++k) {
        // ---------------- w0: scan chunk k (lane = row) ----------------
        if (wid == 0 && k < NCH) {
            const float* xr = &xt[k % D][lane][0];
            float*       vr = &vb[k & 1][lane][0];
            unsigned bits = 0u;
            if (k == 0) {
                // general machine: t=0 edge (spike at 0 opens no window)
                float v = 0.0f, t2 = 0.0f; int c = 0, z = 0; bool s = false;
#pragma unroll 4
                for (int t = 0; t < TC; ++t) {
                    float x  = xr[t];
                    float xe = (z > 0) ? 0.0f : x;
                    float vd = fmaf(-dec, v, v);
                    float a  = vd + xe;
                    float b  = (c == 1) ? xe : a;
                    t2 = (c >= 2) ? VTH : b;
                    s  = t2 > VTH;
                    v  = fminf(t2, VTH);
                    vr[t] = v;
                    bits |= s ? (1u << t) : 0u;
                    c = s ? (c + 1) : (c > 0 ? c - 1 : 0);
                    z = s ? (t > 0 ? 5 : z) : (z > 0 ? z - 1 : 0);
                }
                aa = t2;
                s1 = (int)bits >> 31;
                s2 = (int)(bits << 1) >> 31;
                s3 = (int)(bits << 2) >> 31;
                s4 = (int)(bits << 3) >> 31;
                s5 = (int)(bits << 4) >> 31;
            } else {
#pragma unroll
                for (int g4 = 0; g4 < TC / 4; ++g4) {
                    float4 x4 = *reinterpret_cast<const float4*>(xr + 4 * g4);
                    float xs[4] = {x4.x, x4.y, x4.z, x4.w};
                    float vs[4];
#pragma unroll
                    for (int qq = 0; qq < 4; ++qq) {
                        const int t = 4 * g4 + qq;
                        int w1m = s2 | s3 | s4;
                        int xm  = __float_as_int(xs[qq]) & ~(w1m | s5);
                        float vd  = fmaf(-dec, aa, aa);
                        float sum = vd + __int_as_float(xm);
                        float aan = __int_as_float(__float_as_int(sum) & ~s1);
                        int   sm  = __float_as_int(VTH - aan) >> 31;
                        vs[qq] = fminf(aan, VTH);
                        bits |= (1u << t) & (unsigned)sm;
                        s5 = s4; s4 = s3; s3 = s2; s2 = s1; s1 = sm;
                        aa = aan;
                    }
                    *reinterpret_cast<float4*>(vr + 4 * g4) =
                        make_float4(vs[0], vs[1], vs[2], vs[3]);
                }
            }
            sb[k & 3][lane] = bits;
        }

        // ------ w1: prefetch + coalesced v/s store (chunk k-1) ------
        if (wid == 1) {
            if (k + 3 < NCH)
                cp_chunk(xg0 + (size_t)(k + 3) * TC, &xt[(k + 3) % D][0][0], q, m);
            const int c = k - 1;
            if (c >= 0 && c < NCH) {
                const float* vbb = &vb[c & 1][0][0];
                float* vout = v_out + (size_t)row0 * T_LEN + (size_t)c * TC;
                float* sout = s_out + (size_t)row0 * T_LEN + (size_t)c * TC;
#pragma unroll
                for (int r = 0; r < 8; ++r) {
                    const int rr = 4 * r + q;
                    float4 v4 = *reinterpret_cast<const float4*>(vbb + rr * STRW + 4 * m);
                    *reinterpret_cast<float4*>(vout + (size_t)rr * T_LEN + 4 * m) = v4;
                    const unsigned msk = sb[c & 3][rr];
                    float sf[4];
#pragma unroll
                    for (int j = 0; j < 4; ++j)
                        sf[j] = __int_as_float(
                            ((int)(msk << (31 - (4 * m + j))) >> 31) & 0x3f800000);
                    *reinterpret_cast<float4*>(sout + (size_t)rr * T_LEN + 4 * m) =
                        make_float4(sf[0], sf[1], sf[2], sf[3]);
                }
            }
            asm volatile("cp.async.wait_group 2;\n" ::: "memory");
        }

        // ------ w2: coalesced dv (chunk k-2) ------
        if (wid == 2) {
            const int c = k - 2;
            if (c >= 0 && c < NCH) {
                // phase A: lane computes zero-window mask for its own row
                unsigned mm = sb[c & 3][lane];
                unsigned mp = (c > 0) ? sb[(c - 1) & 3][lane] : 0u;
                unsigned mn = (c + 1 < NCH) ? (sb[(c + 1) & 3][lane] & 1u) : 0u;
                if (c == 0) mm &= ~1u;   // spike at t=0 zeroes nothing
                if (c == 1) mp &= ~1u;
                unsigned long long W = ((unsigned long long)mm << 5) | (mp >> 27)
                                     | ((unsigned long long)mn << 37);
                W |= W >> 1; W |= W >> 2; W |= W >> 3;
                Wsh[lane] = (unsigned)W;   // bit t set -> zero dv[c*TC + t]
                __syncwarp();
                // phase B: coalesced store pass
                const float* xb = &xt[c % D][0][0];
                float* dout = dv_out + (size_t)row0 * T_LEN + (size_t)c * TC;
#pragma unroll
                for (int r = 0; r < 8; ++r) {
                    const int rr = 4 * r + q;
                    const unsigned V = Wsh[rr];
                    float4 x4 = *reinterpret_cast<const float4*>(xb + rr * STRW + 4 * m);
                    int xv[4] = {__float_as_int(x4.x), __float_as_int(x4.y),
                                 __float_as_int(x4.z), __float_as_int(x4.w)};
                    float rv[4];
#pragma unroll
                    for (int j = 0; j < 4; ++j) {
                        const int t = 4 * m + j;
                        int mskb = (int)(V << (31 - t)) >> 31;
                        rv[j] = __int_as_float(xv[j] & ~mskb);
                    }
                    *reinterpret_cast<float4*>(dout + (size_t)rr * T_LEN + 4 * m) =
                        make_float4(rv[0], rv[1], rv[2], rv[3]);
                }
            }
        }

        __syncthreads();
    }
}

extern "C" void kernel_launch(void* const* d_in, const int* in_sizes, int n_in,
                              void* d_out, int out_size)
{
    const float* ode     = (const float*)d_in[0];
    const float* decay_p = (const float*)d_in[1];
    float*       out     = (float*)d_out;

    const int BT = in_sizes[0];
    const int B  = BT / T_LEN;

    float* v_out  = out;
    float* s_out  = out + (size_t)BT;
    float* dv_out = out + (size_t)2 * BT;

    lif_fused<<<B / ROWS, 96>>>(ode, decay_p, v_out, s_out, dv_out);
}

// round 9
// speedup vs baseline: 2.2846x; 1.2923x over previous
#include <cuda_runtime.h>
#include <cstdint>

static constexpr int   T_LEN = 4096;
static constexpr int   TC    = 32;            // steps per chunk
static constexpr int   NCH   = T_LEN / TC;    // 128
static constexpr int   ROWS  = 32;            // rows per block
static constexpr int   XD    = 8;             // x-tile ring depth
static constexpr int   VD    = 4;             // v buffer ring depth
static constexpr int   SD    = 8;             // spike-bit ring depth
static constexpr int   STRW  = 36;            // padded words/row (bank-safe)
static constexpr float VTH   = 1.27f;

// Coalesced chunk copy-issue: lane (q,m) loads row 4r+q, bytes 16m, r=0..7.
// Each cp.async warp-op covers 4 rows x 128B = 4 full lines (4 wavefronts).
// NOTE: does NOT commit — caller commits (possibly empty) groups so the
// wait_group depth accounting stays exact on the tail.
__device__ __forceinline__ void cp_chunk_issue(const float* gchunk, float* stile,
                                               int q, int m)
{
#pragma unroll
    for (int r = 0; r < 8; ++r) {
        const int rr = 4 * r + q;
        unsigned sa = (unsigned)__cvta_generic_to_shared(stile + rr * STRW + 4 * m);
        asm volatile("cp.async.ca.shared.global [%0], [%1], 16;\n"
                     :: "r"(sa), "l"(gchunk + (size_t)rr * T_LEN + 4 * m));
    }
}

__device__ __forceinline__ void cp_commit()
{
    asm volatile("cp.async.commit_group;\n");
}

__global__ void __launch_bounds__(128)
lif_fused(const float* __restrict__ ode, const float* __restrict__ decay_p,
          float* __restrict__ v_out, float* __restrict__ s_out,
          float* __restrict__ dv_out)
{
    __shared__ float    xt[XD][ROWS][STRW];  // input chunks (ring)
    __shared__ float    vb[VD][ROWS][STRW];  // v values (ring)
    __shared__ unsigned sb[SD][ROWS];        // spike bitmask per chunk (ring)
    __shared__ unsigned Wsh[ROWS];           // dv zero-window mask per row

    const int wid  = threadIdx.x >> 5;
    const int lane = threadIdx.x & 31;
    const int q    = lane >> 3;              // 0..3 : row group
    const int m    = lane & 7;               // 0..7 : 16B segment in chunk
    const int row0 = blockIdx.x * ROWS;
    const float dec = __ldg(decay_p);
    const float* xg0 = ode + (size_t)row0 * T_LEN;

    // scan state (w0): aa = pre-clamp value of previous step,
    // s1..s5 = spike masks (~0 iff spike) for steps t-1..t-5.
    float aa = 0.0f;
    int s1 = 0, s2 = 0, s3 = 0, s4 = 0, s5 = 0;

    if (wid == 1) {
        cp_chunk_issue(xg0 + 0 * TC, &xt[0][0][0], q, m); cp_commit();
        cp_chunk_issue(xg0 + 1 * TC, &xt[1][0][0], q, m); cp_commit();
        cp_chunk_issue(xg0 + 2 * TC, &xt[2][0][0], q, m); cp_commit();
        asm volatile("cp.async.wait_group 2;\n" ::: "memory");  // chunk 0 ready
    }
    __syncthreads();

    for (int k = 0; k < NCH + 2; ++k) {
        // ---------------- w0: scan chunk k (lane = row) ----------------
        if (wid == 0 && k < NCH) {
            const float* xr = &xt[k % XD][lane][0];
            float*       vr = &vb[k % VD][lane][0];
            unsigned bits = 0u;
            if (k == 0) {
                // general machine: t=0 edge (spike at 0 opens no window)
                float v = 0.0f, t2 = 0.0f; int c = 0, z = 0; bool s = false;
#pragma unroll 4
                for (int t = 0; t < TC; ++t) {
                    float x  = xr[t];
                    float xe = (z > 0) ? 0.0f : x;
                    float vd = fmaf(-dec, v, v);
                    float a  = vd + xe;
                    float b  = (c == 1) ? xe : a;
                    t2 = (c >= 2) ? VTH : b;
                    s  = t2 > VTH;
                    v  = fminf(t2, VTH);
                    vr[t] = v;
                    bits |= s ? (1u << t) : 0u;
                    c = s ? (c + 1) : (c > 0 ? c - 1 : 0);
                    z = s ? (t > 0 ? 5 : z) : (z > 0 ? z - 1 : 0);
                }
                aa = t2;
                s1 = (int)bits >> 31;
                s2 = (int)(bits << 1) >> 31;
                s3 = (int)(bits << 2) >> 31;
                s4 = (int)(bits << 3) >> 31;
                s5 = (int)(bits << 4) >> 31;
            } else {
                // hoist whole chunk into registers: LDS latency off the chain
                float4 xv[8];
#pragma unroll
                for (int g4 = 0; g4 < 8; ++g4)
                    xv[g4] = *reinterpret_cast<const float4*>(xr + 4 * g4);
#pragma unroll
                for (int g4 = 0; g4 < 8; ++g4) {
                    float xs[4] = {xv[g4].x, xv[g4].y, xv[g4].z, xv[g4].w};
                    float vs[4];
#pragma unroll
                    for (int qq = 0; qq < 4; ++qq) {
                        const int t = 4 * g4 + qq;
                        int w1m = s2 | s3 | s4;
                        int xm  = __float_as_int(xs[qq]) & ~(w1m | s5);
                        float vd  = fmaf(-dec, aa, aa);
                        float sum = vd + __int_as_float(xm);
                        float aan = __int_as_float(__float_as_int(sum) & ~s1);
                        int   sm  = __float_as_int(VTH - aan) >> 31;
                        vs[qq] = fminf(aan, VTH);
                        bits |= (1u << t) & (unsigned)sm;
                        s5 = s4; s4 = s3; s3 = s2; s2 = s1; s1 = sm;
                        aa = aan;
                    }
                    *reinterpret_cast<float4*>(vr + 4 * g4) =
                        make_float4(vs[0], vs[1], vs[2], vs[3]);
                }
            }
            sb[k % SD][lane] = bits;
        }

        // ------ w1: prefetch + coalesced v store (chunk k-1) ------
        if (wid == 1) {
            if (k + 3 < NCH)
                cp_chunk_issue(xg0 + (size_t)(k + 3) * TC, &xt[(k + 3) % XD][0][0], q, m);
            cp_commit();   // ALWAYS commit (empty group on tail) — keeps
                           // wait_group depth exact so chunk k+1 is provably done
            const int c = k - 1;
            if (c >= 0 && c < NCH) {
                const float* vbb = &vb[c % VD][0][0];
                float* vout = v_out + (size_t)row0 * T_LEN + (size_t)c * TC;
#pragma unroll
                for (int r = 0; r < 8; ++r) {
                    const int rr = 4 * r + q;
                    float4 v4 = *reinterpret_cast<const float4*>(vbb + rr * STRW + 4 * m);
                    *reinterpret_cast<float4*>(vout + (size_t)rr * T_LEN + 4 * m) = v4;
                }
            }
            asm volatile("cp.async.wait_group 2;\n" ::: "memory");
        }

        // ------ w2: coalesced s store (chunk k-1) ------
        if (wid == 2) {
            const int c = k - 1;
            if (c >= 0 && c < NCH) {
                float* sout = s_out + (size_t)row0 * T_LEN + (size_t)c * TC;
#pragma unroll
                for (int r = 0; r < 8; ++r) {
                    const int rr = 4 * r + q;
                    const unsigned msk = sb[c % SD][rr];
                    float sf[4];
#pragma unroll
                    for (int j = 0; j < 4; ++j)
                        sf[j] = __int_as_float(
                            ((int)(msk << (31 - (4 * m + j))) >> 31) & 0x3f800000);
                    *reinterpret_cast<float4*>(sout + (size_t)rr * T_LEN + 4 * m) =
                        make_float4(sf[0], sf[1], sf[2], sf[3]);
                }
            }
        }

        // ------ w3: coalesced dv (chunk k-2) ------
        if (wid == 3) {
            const int c = k - 2;
            if (c >= 0 && c < NCH) {
                // phase A: lane computes zero-window mask for its own row
                unsigned mm = sb[c % SD][lane];
                unsigned mp = (c > 0) ? sb[(c - 1) % SD][lane] : 0u;
                unsigned mn = (c + 1 < NCH) ? (sb[(c + 1) % SD][lane] & 1u) : 0u;
                if (c == 0) mm &= ~1u;   // spike at t=0 zeroes nothing
                if (c == 1) mp &= ~1u;
                unsigned long long W = ((unsigned long long)mm << 5) | (mp >> 27)
                                     | ((unsigned long long)mn << 37);
                W |= W >> 1; W |= W >> 2; W |= W >> 3;
                Wsh[lane] = (unsigned)W;   // bit t set -> zero dv[c*TC + t]
                __syncwarp();
                // phase B: coalesced store pass
                const float* xb = &xt[c % XD][0][0];
                float* dout = dv_out + (size_t)row0 * T_LEN + (size_t)c * TC;
#pragma unroll
                for (int r = 0; r < 8; ++r) {
                    const int rr = 4 * r + q;
                    const unsigned V = Wsh[rr];
                    float4 x4 = *reinterpret_cast<const float4*>(xb + rr * STRW + 4 * m);
                    int xw[4] = {__float_as_int(x4.x), __float_as_int(x4.y),
                                 __float_as_int(x4.z), __float_as_int(x4.w)};
                    float rv[4];
#pragma unroll
                    for (int j = 0; j < 4; ++j) {
                        const int t = 4 * m + j;
                        int mskb = (int)(V << (31 - t)) >> 31;
                        rv[j] = __int_as_float(xw[j] & ~mskb);
                    }
                    *reinterpret_cast<float4*>(dout + (size_t)rr * T_LEN + 4 * m) =
                        make_float4(rv[0], rv[1], rv[2], rv[3]);
                }
                __syncwarp();   // protect Wsh before next iteration's phase A
            }
        }

        __syncthreads();
    }
}

extern "C" void kernel_launch(void* const* d_in, const int* in_sizes, int n_in,
                              void* d_out, int out_size)
{
    const float* ode     = (const float*)d_in[0];
    const float* decay_p = (const float*)d_in[1];
    float*       out     = (float*)d_out;

    const int BT = in_sizes[0];
    const int B  = BT / T_LEN;

    float* v_out  = out;
    float* s_out  = out + (size_t)BT;
    float* dv_out = out + (size_t)2 * BT;

    lif_fused<<<B / ROWS, 128>>>(ode, decay_p, v_out, s_out, dv_out);
}

// round 10
// speedup vs baseline: 2.2952x; 1.0047x over previous
#include <cuda_runtime.h>
#include <cstdint>

static constexpr int   T_LEN = 4096;
static constexpr int   TC    = 64;            // steps per chunk
static constexpr int   NCH   = T_LEN / TC;    // 64
static constexpr int   ROWS  = 32;            // rows per block
static constexpr int   XD    = 5;             // x-tile ring depth (span k-2..k+2)
static constexpr int   VD    = 2;             // v buffer ring depth
static constexpr int   SD    = 4;             // spike-bit ring depth (span k-3..k)
static constexpr int   STRW  = 68;            // padded words/row (bank-safe, 16B-aligned)
static constexpr float VTH   = 1.27f;

// Coalesced chunk copy-issue: lane (q2=lane>>4, m2=lane&15) covers row 2r+q2,
// bytes 16*m2, r=0..15. Each warp-op = 2 rows x 256B = 4 full lines.
// Does NOT commit — caller commits (possibly empty) groups so wait_group
// depth accounting stays exact on the tail (round-8 invariant).
__device__ __forceinline__ void cp_chunk_issue(const float* gchunk, float* stile,
                                               int q2, int m2)
{
#pragma unroll
    for (int r = 0; r < 16; ++r) {
        const int rr = 2 * r + q2;
        unsigned sa = (unsigned)__cvta_generic_to_shared(stile + rr * STRW + 4 * m2);
        asm volatile("cp.async.ca.shared.global [%0], [%1], 16;\n"
                     :: "r"(sa), "l"(gchunk + (size_t)rr * T_LEN + 4 * m2));
    }
}

__device__ __forceinline__ void cp_commit()
{
    asm volatile("cp.async.commit_group;\n");
}

__global__ void __launch_bounds__(128)
lif_fused(const float* __restrict__ ode, const float* __restrict__ decay_p,
          float* __restrict__ v_out, float* __restrict__ s_out,
          float* __restrict__ dv_out)
{
    __shared__ float    xt[XD][ROWS][STRW];   // input chunks (ring)
    __shared__ float    vb[VD][ROWS][STRW];   // v values (ring)
    __shared__ unsigned sb[SD][ROWS][2];      // spike bits per chunk (2 words)
    __shared__ unsigned Wsh[ROWS][2];         // dv zero-window per row (2 words)

    const int wid  = threadIdx.x >> 5;
    const int lane = threadIdx.x & 31;
    const int q2   = lane >> 4;               // 0..1 : row parity group
    const int m2   = lane & 15;               // 0..15: 16B segment in chunk
    const int row0 = blockIdx.x * ROWS;
    const float dec = __ldg(decay_p);
    const float* xg0 = ode + (size_t)row0 * T_LEN;

    // scan state (w0): aa = pre-clamp value of previous step,
    // s1..s5 = spike masks (~0 iff spike) for steps t-1..t-5.
    float aa = 0.0f;
    int s1 = 0, s2 = 0, s3 = 0, s4 = 0, s5 = 0;

    if (wid == 1) {
        cp_chunk_issue(xg0 + 0 * TC, &xt[0][0][0], q2, m2); cp_commit();
        cp_chunk_issue(xg0 + 1 * TC, &xt[1][0][0], q2, m2); cp_commit();
        asm volatile("cp.async.wait_group 1;\n" ::: "memory");  // chunk 0 ready
    }
    __syncthreads();

    for (int k = 0; k < NCH + 2; ++k) {
        // ---------------- w0: scan chunk k (lane = row) ----------------
        if (wid == 0 && k < NCH) {
            const float* xr = &xt[k % XD][lane][0];
            float*       vr = &vb[k % VD][lane][0];
            unsigned bits0 = 0u, bits1 = 0u;
            if (k == 0) {
                // general machine over the whole first chunk (t=0 edge exact)
                float v = 0.0f, t2 = 0.0f; int c = 0, z = 0; bool s = false;
#pragma unroll 4
                for (int t = 0; t < TC; ++t) {
                    float x  = xr[t];
                    float xe = (z > 0) ? 0.0f : x;
                    float vd = fmaf(-dec, v, v);
                    float a  = vd + xe;
                    float b  = (c == 1) ? xe : a;
                    t2 = (c >= 2) ? VTH : b;
                    s  = t2 > VTH;
                    v  = fminf(t2, VTH);
                    vr[t] = v;
                    if (t < 32) bits0 |= s ? (1u << t) : 0u;
                    else        bits1 |= s ? (1u << (t - 32)) : 0u;
                    c = s ? (c + 1) : (c > 0 ? c - 1 : 0);
                    z = s ? (t > 0 ? 5 : z) : (z > 0 ? z - 1 : 0);
                }
                aa = t2;
                s1 = (int)bits1 >> 31;
                s2 = (int)(bits1 << 1) >> 31;
                s3 = (int)(bits1 << 2) >> 31;
                s4 = (int)(bits1 << 3) >> 31;
                s5 = (int)(bits1 << 4) >> 31;
            } else {
#pragma unroll
                for (int half = 0; half < 2; ++half) {
                    // hoist half-chunk into registers: LDS latency off the chain
                    float4 xv[8];
#pragma unroll
                    for (int g4 = 0; g4 < 8; ++g4)
                        xv[g4] = *reinterpret_cast<const float4*>(xr + 32 * half + 4 * g4);
                    unsigned bits = 0u;
#pragma unroll
                    for (int g4 = 0; g4 < 8; ++g4) {
                        float xs[4] = {xv[g4].x, xv[g4].y, xv[g4].z, xv[g4].w};
                        float vs[4];
#pragma unroll
                        for (int qq = 0; qq < 4; ++qq) {
                            const int t = 4 * g4 + qq;
                            int w1m = s2 | s3 | s4;
                            int xm  = __float_as_int(xs[qq]) & ~(w1m | s5);
                            float vd  = fmaf(-dec, aa, aa);
                            float sum = vd + __int_as_float(xm);
                            float aan = __int_as_float(__float_as_int(sum) & ~s1);
                            int   sm  = __float_as_int(VTH - aan) >> 31;
                            vs[qq] = fminf(aan, VTH);
                            bits |= (1u << t) & (unsigned)sm;
                            s5 = s4; s4 = s3; s3 = s2; s2 = s1; s1 = sm;
                            aa = aan;
                        }
                        *reinterpret_cast<float4*>(vr + 32 * half + 4 * g4) =
                            make_float4(vs[0], vs[1], vs[2], vs[3]);
                    }
                    if (half == 0) bits0 = bits; else bits1 = bits;
                }
            }
            sb[k % SD][lane][0] = bits0;
            sb[k % SD][lane][1] = bits1;
        }

        // ------ w1: prefetch + coalesced v store (chunk k-1) ------
        if (wid == 1) {
            if (k + 2 < NCH)
                cp_chunk_issue(xg0 + (size_t)(k + 2) * TC, &xt[(k + 2) % XD][0][0], q2, m2);
            cp_commit();   // ALWAYS commit (empty on tail) — keeps wait_group
                           // depth exact so chunk k+1 is provably complete
            const int c = k - 1;
            if (c >= 0 && c < NCH) {
                const float* vbb = &vb[c % VD][0][0];
                float* vout = v_out + (size_t)row0 * T_LEN + (size_t)c * TC;
#pragma unroll
                for (int r = 0; r < 16; ++r) {
                    const int rr = 2 * r + q2;
                    float4 v4 = *reinterpret_cast<const float4*>(vbb + rr * STRW + 4 * m2);
                    *reinterpret_cast<float4*>(vout + (size_t)rr * T_LEN + 4 * m2) = v4;
                }
            }
            asm volatile("cp.async.wait_group 1;\n" ::: "memory");
        }

        // ------ w2: coalesced s store (chunk k-1) ------
        if (wid == 2) {
            const int c = k - 1;
            if (c >= 0 && c < NCH) {
                float* sout = s_out + (size_t)row0 * T_LEN + (size_t)c * TC;
                const int h  = m2 >> 3;            // bit word for this segment
                const int tb = 4 * (m2 & 7);       // bit base within word
#pragma unroll
                for (int r = 0; r < 16; ++r) {
                    const int rr = 2 * r + q2;
                    const unsigned msk = sb[c % SD][rr][h];
                    float sf[4];
#pragma unroll
                    for (int j = 0; j < 4; ++j)
                        sf[j] = __int_as_float(
                            ((int)(msk << (31 - (tb + j))) >> 31) & 0x3f800000);
                    *reinterpret_cast<float4*>(sout + (size_t)rr * T_LEN + 4 * m2) =
                        make_float4(sf[0], sf[1], sf[2], sf[3]);
                }
            }
        }

        // ------ w3: coalesced dv (chunk k-2) ------
        if (wid == 3) {
            const int c = k - 2;
            if (c >= 0 && c < NCH) {
                // phase A: lane computes zero-window words for its own row
                const unsigned* sbc = sb[c % SD][lane];
#pragma unroll
                for (int h = 0; h < 2; ++h) {
                    unsigned mm, mp, mn;
                    if (h == 0) {
                        mm = sbc[0];
                        mp = (c > 0) ? sb[(c - 1) % SD][lane][1] : 0u;
                        mn = sbc[1] & 1u;
                        if (c == 0) mm &= ~1u;   // spike at t=0 zeroes nothing
                    } else {
                        mm = sbc[1];
                        mp = sbc[0];
                        if (c == 0) mp &= ~1u;
                        mn = (c + 1 < NCH) ? (sb[(c + 1) % SD][lane][0] & 1u) : 0u;
                    }
                    unsigned long long W = ((unsigned long long)mm << 5) | (mp >> 27)
                                         | ((unsigned long long)mn << 37);
                    W |= W >> 1; W |= W >> 2; W |= W >> 3;
                    Wsh[lane][h] = (unsigned)W;  // bit t set -> zero dv[..+32h+t]
                }
                __syncwarp();
                // phase B: coalesced store pass
                const float* xb = &xt[c % XD][0][0];
                float* dout = dv_out + (size_t)row0 * T_LEN + (size_t)c * TC;
                const int h  = m2 >> 3;
                const int tb = 4 * (m2 & 7);
#pragma unroll
                for (int r = 0; r < 16; ++r) {
                    const int rr = 2 * r + q2;
                    const unsigned V = Wsh[rr][h];
                    float4 x4 = *reinterpret_cast<const float4*>(xb + rr * STRW + 4 * m2);
                    int xw[4] = {__float_as_int(x4.x), __float_as_int(x4.y),
                                 __float_as_int(x4.z), __float_as_int(x4.w)};
                    float rv[4];
#pragma unroll
                    for (int j = 0; j < 4; ++j) {
                        int mskb = (int)(V << (31 - (tb + j))) >> 31;
                        rv[j] = __int_as_float(xw[j] & ~mskb);
                    }
                    *reinterpret_cast<float4*>(dout + (size_t)rr * T_LEN + 4 * m2) =
                        make_float4(rv[0], rv[1], rv[2], rv[3]);
                }
                __syncwarp();   // protect Wsh before next iteration's phase A
            }
        }

        __syncthreads();
    }
}

extern "C" void kernel_launch(void* const* d_in, const int* in_sizes, int n_in,
                              void* d_out, int out_size)
{
    const float* ode     = (const float*)d_in[0];
    const float* decay_p = (const float*)d_in[1];
    float*       out     = (float*)d_out;

    const int BT = in_sizes[0];
    const int B  = BT / T_LEN;

    float* v_out  = out;
    float* s_out  = out + (size_t)BT;
    float* dv_out = out + (size_t)2 * BT;

    lif_fused<<<B / ROWS, 128>>>(ode, decay_p, v_out, s_out, dv_out);
}